// round 14
// baseline (speedup 1.0000x reference)
#include <cuda_runtime.h>
#include <math.h>
#define BB 16
#define CC 192
#define SS 1024
#define NI 384
#define NHD 12
#define DHD 32
#define NROWS (BB*SS)

__device__ float g_seq[NROWS*CC], g_hln[NROWS*CC], g_up[NROWS*768], g_xact[NROWS*NI];
__device__ float g_qk[NROWS*768], g_gates[NROWS*64], g_hout[NROWS*NI];
__device__ float g_t1[NROWS*CC], g_y[NROWS*CC], g_conv[NROWS*CC];
__device__ float g_wcomb[768*64], g_gbias[64], g_wconv[1728*CC], g_wqk[384*768];
__device__ float g_bnpart[256*2*CC], g_bna[CC], g_bnb[CC];

__device__ __forceinline__ float logsigf(float v){return (v>=0.f)?-log1pf(expf(-v)):v-log1pf(expf(v));}
__device__ __forceinline__ float siluf(float v){return v/(1.f+__expf(-v));}
__device__ __forceinline__ void cpa16(void* s,const void* g,bool p){
    unsigned sa=(unsigned)__cvta_generic_to_shared(s);
    int sz=p?16:0;
    asm volatile("cp.async.cg.shared.global [%0],[%1],16,%2;"::"r"(sa),"l"(g),"r"(sz));
}
#define CPA_COMMIT asm volatile("cp.async.commit_group;")
#define CPA_WAIT1  asm volatile("cp.async.wait_group 1;")
#define CPA_WAIT0  asm volatile("cp.async.wait_group 0;")

__global__ void prep_gates_kernel(const float* wq,const float* wk,const float* wi,const float* wf){
    int gid=blockIdx.x*8+(threadIdx.x>>5);
    int lane=threadIdx.x&31;
    int r=gid%384, c=gid/384;
    const float* W=(c<12)?wi:wf; int cc=(c<12)?c:c-12;
    float s=0.f;
    for(int j=lane;j<384;j+=32)
        s+=wq[r*384+j]*W[j*12+cc]+wk[r*384+j]*W[(384+j)*12+cc];
#pragma unroll
    for(int o=16;o>0;o>>=1) s+=__shfl_xor_sync(~0u,s,o);
    if(lane==0) g_wcomb[r*64+c]=s;
}
__global__ void prep_gates2_kernel(const float* wi,const float* wf,const float* bi,const float* bf){
    int idx=blockIdx.x*256+threadIdx.x;
    if(idx<64) g_gbias[idx]=(idx<12)?bi[idx]:(idx<24?bf[idx-12]:0.f);
    if(idx>=768*64) return;
    int r=idx>>6,c=idx&63;
    if(r<384&&c<24) return;
    float v=0.f;
    if(c<24&&r>=384){
        const float* W=(c<12)?wi:wf; int cc=(c<12)?c:c-12;
        v=W[(768+(r-384))*12+cc];
    }
    g_wcomb[idx]=v;
}

__global__ void prep_wqk_kernel(const float* wq,const float* wk){
    int idx=blockIdx.x*256+threadIdx.x;
    if(idx>=384*768) return;
    int k=idx/768,n=idx-k*768;
    g_wqk[idx]=(n<384)?wq[k*384+n]:wk[k*384+(n-384)];
}

__global__ void prep_wconv_kernel(const float* w){
    int idx=blockIdx.x*256+threadIdx.x;
    if(idx>=192*1728) return;
    int co=idx/1728,rem=idx-co*1728,ci=rem/9,tap=rem-ci*9;
    g_wconv[(tap*192+ci)*192+co]=w[idx];
}

__global__ void transpose_ln_kernel(const float* x,const float* lnw,const float* lnb){
    __shared__ float tile[CC][33];
    int b=blockIdx.x>>5,s0=(blockIdx.x&31)*32,tid=threadIdx.x;
    for(int i=tid;i<CC*32;i+=256){int c=i>>5,si=i&31; tile[c][si]=x[((size_t)b*CC+c)*SS+s0+si];}
    __syncthreads();
    int warp=tid>>5,lane=tid&31;
    for(int t=0;t<4;t++){
        int si=warp*4+t; float v[6],sum=0.f,sq=0.f;
#pragma unroll
        for(int u=0;u<6;u++){v[u]=tile[lane+32*u][si];sum+=v[u];sq+=v[u]*v[u];}
#pragma unroll
        for(int o=16;o>0;o>>=1){sum+=__shfl_xor_sync(~0u,sum,o);sq+=__shfl_xor_sync(~0u,sq,o);}
        float mu=sum*(1.f/192.f),var=sq*(1.f/192.f)-mu*mu,rstd=rsqrtf(var+1e-5f);
        size_t row=(size_t)b*SS+s0+si;
#pragma unroll
        for(int u=0;u<6;u++){int c=lane+32*u; g_seq[row*CC+c]=v[u]; g_hln[row*CC+c]=(v[u]-mu)*rstd*lnw[c]+lnb[c];}
    }
}

// ---- Hybrid GEMM: 5/8 of M-tiles use TF32 HMMA, 3/8 use FFMA (idle fma pipe).
// SRC:0 plain,1 gates-concat,2 conv2-gather. ACT:0 none,1 silu,2 gates,3 silu+seq+t1->y ----
template<int SRC,int ACT>
__device__ __forceinline__ void epi_store(float* Cp,int ldc,int row,int col,float v,const float* bias){
    size_t ro=(size_t)row*ldc+col;
    if(ACT==2){
        v+=g_gbias[col];
        if(col>=12&&col<24) v=logsigf(v);
    } else {
        if(bias) v+=bias[col];
        if(ACT==1) v=siluf(v);
        if(ACT==3) v=siluf(v)+g_seq[ro]+g_t1[ro];
    }
    Cp[ro]=v;
}

template<int SRC,int ACT>
__global__ void __launch_bounds__(256) tgemm(const float* A,const float* B,float* Cp,int K,int lda,int ldb,int ldc,const float* bias){
    __shared__ float As[3][128][20];
    __shared__ float Bs[3][16][72];
    int tid=threadIdx.x,lane=tid&31,wrp=tid>>5;
    int wm=wrp&3,wn=wrp>>2;
    int bm=blockIdx.y*128,bn=blockIdx.x*64;
    int g=lane>>2,tg=lane&3;
    const bool ffma=((blockIdx.y&7)<3);
    float accM[2][4][4]={};
    float accF[8][4]={};
    int tM2=(tid>>4)*8,tN2=(tid&15)*4;
    int T=K/16;

    int idA0=tid*2,rA0=idA0>>2,kqA0=(idA0&3)<<2;
    int idA1=tid*2+1,rA1=idA1>>2,kqA1=(idA1&3)<<2;
    int krB=tid>>4,nqB=(tid&15)<<2;

#define LOADTILE(t,buf) { \
        int k0=(t)*16; \
        const float *sa0,*sa1; bool p0=true,p1=true; \
        if(SRC==0){ \
            sa0=A+(size_t)(bm+rA0)*lda+k0+kqA0; \
            sa1=A+(size_t)(bm+rA1)*lda+k0+kqA1; \
        } else if(SRC==1){ \
            int ka=k0+kqA0,kb=k0+kqA1; \
            sa0=(ka<384)?(g_xact+(size_t)(bm+rA0)*384+ka):(g_up+(size_t)(bm+rA0)*768+(ka-384)); \
            sa1=(kb<384)?(g_xact+(size_t)(bm+rA1)*384+kb):(g_up+(size_t)(bm+rA1)*768+(kb-384)); \
        } else { \
            int tap=k0/192,rem=k0-tap*192; \
            int dh=tap/3-1,dw=tap-(tap/3)*3-1,off=dh*32+dw; \
            int row0=bm+rA0,pp0=row0&1023,hh0=(pp0>>5)+dh,ww0=(pp0&31)+dw; \
            int row1=bm+rA1,pp1=row1&1023,hh1=(pp1>>5)+dh,ww1=(pp1&31)+dw; \
            p0=((unsigned)hh0<32u&&(unsigned)ww0<32u); \
            p1=((unsigned)hh1<32u&&(unsigned)ww1<32u); \
            sa0=p0?(g_y+(size_t)(row0+off)*192+rem+kqA0):g_y; \
            sa1=p1?(g_y+(size_t)(row1+off)*192+rem+kqA1):g_y; \
        } \
        cpa16(&As[buf][rA0][kqA0],sa0,p0); \
        cpa16(&As[buf][rA1][kqA1],sa1,p1); \
        cpa16(&Bs[buf][krB][nqB],B+(size_t)(k0+krB)*ldb+bn+nqB,true); \
        CPA_COMMIT; }

    LOADTILE(0,0);
    LOADTILE(1,1);
    for(int t=0;t<T;t++){
        if(t+2<T){ CPA_WAIT1; } else { CPA_WAIT0; }
        __syncthreads();
        if(t+2<T){ int nb=(t+2)%3; LOADTILE(t+2,nb); }
        int buf=t%3;
        if(ffma){
#pragma unroll
            for(int kk=0;kk<16;kk++){
                float a[8];
#pragma unroll
                for(int i=0;i<8;i++) a[i]=As[buf][tM2+i][kk];
                float4 bv=*(const float4*)(&Bs[buf][kk][tN2]);
                float bb[4]={bv.x,bv.y,bv.z,bv.w};
#pragma unroll
                for(int i=0;i<8;i++)
#pragma unroll
                    for(int j=0;j<4;j++) accF[i][j]=fmaf(a[i],bb[j],accF[i][j]);
            }
        } else {
#pragma unroll
            for(int kk=0;kk<16;kk+=8){
                unsigned a[2][4],b[4][2];
#pragma unroll
                for(int mt=0;mt<2;mt++){
                    int m0=wm*32+mt*16;
                    a[mt][0]=__float_as_uint(As[buf][m0+g  ][kk+tg  ]);
                    a[mt][1]=__float_as_uint(As[buf][m0+g+8][kk+tg  ]);
                    a[mt][2]=__float_as_uint(As[buf][m0+g  ][kk+tg+4]);
                    a[mt][3]=__float_as_uint(As[buf][m0+g+8][kk+tg+4]);
                }
#pragma unroll
                for(int nt=0;nt<4;nt++){
                    int n0=wn*32+nt*8;
                    b[nt][0]=__float_as_uint(Bs[buf][kk+tg  ][n0+g]);
                    b[nt][1]=__float_as_uint(Bs[buf][kk+tg+4][n0+g]);
                }
#pragma unroll
                for(int mt=0;mt<2;mt++)
#pragma unroll
                    for(int nt=0;nt<4;nt++)
                        asm volatile("mma.sync.aligned.m16n8k8.row.col.f32.tf32.tf32.f32 {%0,%1,%2,%3},{%4,%5,%6,%7},{%8,%9},{%0,%1,%2,%3};"
                            : "+f"(accM[mt][nt][0]),"+f"(accM[mt][nt][1]),"+f"(accM[mt][nt][2]),"+f"(accM[mt][nt][3])
                            : "r"(a[mt][0]),"r"(a[mt][1]),"r"(a[mt][2]),"r"(a[mt][3]),"r"(b[nt][0]),"r"(b[nt][1]));
            }
        }
    }
#undef LOADTILE
    if(ffma){
#pragma unroll
        for(int i=0;i<8;i++)
#pragma unroll
            for(int j=0;j<4;j++)
                epi_store<SRC,ACT>(Cp,ldc,bm+tM2+i,bn+tN2+j,accF[i][j],bias);
    } else {
#pragma unroll
        for(int mt=0;mt<2;mt++){
            int r1=bm+wm*32+mt*16+g;
#pragma unroll
            for(int nt=0;nt<4;nt++){
                int cb=bn+wn*32+nt*8+2*tg;
                epi_store<SRC,ACT>(Cp,ldc,r1,  cb,  accM[mt][nt][0],bias);
                epi_store<SRC,ACT>(Cp,ldc,r1,  cb+1,accM[mt][nt][1],bias);
                epi_store<SRC,ACT>(Cp,ldc,r1+8,cb,  accM[mt][nt][2],bias);
                epi_store<SRC,ACT>(Cp,ldc,r1+8,cb+1,accM[mt][nt][3],bias);
            }
        }
    }
}

__global__ void conv1d_kernel(const float* ck,const float* cb){
    int row=blockIdx.x,i=threadIdx.x,s=row&1023;
    float acc=cb[i];
    const float* base=g_up+(size_t)row*768+i;
#pragma unroll
    for(int t=0;t<4;t++){int sp=s-3+t; if(sp>=0)acc=fmaf(base[(t-3)*768],ck[i*4+t],acc);}
    g_xact[(size_t)row*NI+i]=siluf(acc);
}

// ---- scan v2: warp0 computes (reductions pipelined 1 step behind), warps1-3 prefetch ----
#define TT 32
__device__ __forceinline__ void scan_load_tile(int tile,int buf,int lt,int nth,
    size_t r0,int head,float ksc,
    float (*sQ)[TT][DHD],float (*sK)[TT][DHD],float (*sV)[TT][DHD],
    float (*sZ)[TT][DHD],float (*sX)[TT][DHD],float (*sI)[TT],float (*sF)[TT])
{
    size_t base=(r0+(size_t)tile*TT);
    for(int u=lt;u<1280;u+=nth){
        int arr=u>>8,rem=u&255,step=rem>>3,l4=(rem&7)<<2;
        size_t row=base+step;
        float4 v;
        if(arr==0)      v=*(const float4*)(g_qk  +row*768+     head*DHD+l4);
        else if(arr==1){v=*(const float4*)(g_qk  +row*768+384+ head*DHD+l4);
                        v.x*=ksc;v.y*=ksc;v.z*=ksc;v.w*=ksc;}
        else if(arr==2) v=*(const float4*)(g_up  +row*768+     head*DHD+l4);
        else if(arr==3) v=*(const float4*)(g_up  +row*768+384+ head*DHD+l4);
        else            v=*(const float4*)(g_xact+row*384+     head*DHD+l4);
        float* dst=(arr==0)?&sQ[buf][step][l4]:(arr==1)?&sK[buf][step][l4]:
                   (arr==2)?&sV[buf][step][l4]:(arr==3)?&sZ[buf][step][l4]:&sX[buf][step][l4];
        *(float4*)dst=v;
    }
    for(int u=lt;u<2*TT;u+=nth){
        int step=u>>1;
        size_t row=base+step;
        if(u&1) sF[buf][step]=g_gates[row*64+12+head];
        else    sI[buf][step]=g_gates[row*64+head];
    }
}

__global__ void __launch_bounds__(128) scan_kernel(const float* skip,const float* mhw,const float* mhb){
    const int tid=threadIdx.x,lane=tid&31,wid=tid>>5;
    const int bh=blockIdx.x,b=bh/NHD,head=bh-b*NHD,idx=head*DHD+lane;
    __shared__ float sQ[2][TT][DHD],sK[2][TT][DHD],sV[2][TT][DHD],sZ[2][TT][DHD],sX[2][TT][DHD];
    __shared__ float sI[2][TT],sF[2][TT];
    const float ksc=0.17677669529663687f;
    const size_t r0=(size_t)b*SS;

    scan_load_tile(0,0,tid,128,r0,head,ksc,sQ,sK,sV,sZ,sX,sI,sF);
    __syncthreads();

    float C[DHD];
#pragma unroll
    for(int e=0;e<DHD;e++)C[e]=0.f;
    float nl=0.f,m=0.f;
    const float wg=mhw[idx],bg=mhb[idx],skp=skip[idx];

    float pNQ=0.f,pH=0.f,pZ=0.f,pX=0.f;
    size_t pRow=0; int hasp=0;

    const int NTILE=SS/TT;
    for(int tile=0;tile<NTILE;tile++){
        int buf=tile&1;
        if(wid>0){
            if(tile+1<NTILE) scan_load_tile(tile+1,buf^1,tid-32,96,r0,head,ksc,sQ,sK,sV,sZ,sX,sI,sF);
        } else {
            for(int t=0;t<TT;t++){
                float cq=sQ[buf][t][lane],ckk=sK[buf][t][lane],cv=sV[buf][t][lane];
                float cz=sZ[buf][t][lane],cx=sX[buf][t][lane];
                float ci=sI[buf][t],cf=sF[buf][t];
                float mnew=fmaxf(cf+m,ci);
                float fs=__expf(cf+m-mnew),is=__expf(ci-mnew);
                m=mnew;
                nl=fs*nl+is*ckk;
                float isv=is*cv;
                float h0=0.f,h1=0.f,h2=0.f,h3=0.f;
#pragma unroll
                for(int j=0;j<8;j++){
                    float4 k4=*(const float4*)(&sK[buf][t][4*j]),q4=*(const float4*)(&sQ[buf][t][4*j]);
                    C[4*j]  =fmaf(isv,k4.x,fs*C[4*j]);   h0=fmaf(C[4*j],  q4.x,h0);
                    C[4*j+1]=fmaf(isv,k4.y,fs*C[4*j+1]); h1=fmaf(C[4*j+1],q4.y,h1);
                    C[4*j+2]=fmaf(isv,k4.z,fs*C[4*j+2]); h2=fmaf(C[4*j+2],q4.z,h2);
                    C[4*j+3]=fmaf(isv,k4.w,fs*C[4*j+3]); h3=fmaf(C[4*j+3],q4.w,h3);
                }
                float h=(h0+h1)+(h2+h3);
                float nqcur=nl*cq;
                if(hasp){
                    float rq=pNQ,rs=pH,rr=pH*pH;
#pragma unroll
                    for(int o=16;o>0;o>>=1){
                        rq+=__shfl_xor_sync(~0u,rq,o);
                        rs+=__shfl_xor_sync(~0u,rs,o);
                        rr+=__shfl_xor_sync(~0u,rr,o);
                    }
                    float d=fmaxf(fabsf(rq),1.f);
                    float mu=rs*(1.f/32.f),var=rr*(1.f/32.f)-mu*mu;
                    float rstd=rsqrtf(var+1e-5f*d*d);
                    float hn=(pH-mu)*rstd*wg+bg;
                    g_hout[pRow]=(hn+skp*pX)*siluf(pZ);
                }
                pNQ=nqcur; pH=h; pZ=cz; pX=cx; pRow=(r0+(size_t)tile*TT+t)*NI+idx; hasp=1;
            }
        }
        __syncthreads();
    }
    if(wid==0&&hasp){
        float rq=pNQ,rs=pH,rr=pH*pH;
#pragma unroll
        for(int o=16;o>0;o>>=1){
            rq+=__shfl_xor_sync(~0u,rq,o);
            rs+=__shfl_xor_sync(~0u,rs,o);
            rr+=__shfl_xor_sync(~0u,rr,o);
        }
        float d=fmaxf(fabsf(rq),1.f);
        float mu=rs*(1.f/32.f),var=rr*(1.f/32.f)-mu*mu;
        float rstd=rsqrtf(var+1e-5f*d*d);
        float hn=(pH-mu)*rstd*wg+bg;
        g_hout[pRow]=(hn+skp*pX)*siluf(pZ);
    }
}

__global__ void bn_stats_kernel(){
    int c=threadIdx.x,blk=blockIdx.x;
    float s=0.f,q=0.f;
    for(int r=0;r<64;r++){float v=g_conv[((size_t)(blk*64+r))*192+c]; s+=v; q+=v*v;}
    g_bnpart[blk*384+c]=s; g_bnpart[blk*384+192+c]=q;
}
__global__ void bn_reduce_kernel(const float* bng,const float* bnb){
    int c=threadIdx.x;
    float s=0.f,q=0.f;
    for(int b=0;b<256;b++){s+=g_bnpart[b*384+c];q+=g_bnpart[b*384+192+c];}
    float mu=s*(1.f/16384.f),var=q*(1.f/16384.f)-mu*mu;
    float a=bng[c]*rsqrtf(var+1e-5f);
    g_bna[c]=a; g_bnb[c]=bnb[c]-mu*a;
}

__global__ void out_bn_kernel(float* out){
    __shared__ float tile[32][193];
    int b=blockIdx.x>>5,p0=(blockIdx.x&31)*32,tid=threadIdx.x;
    for(int i=tid;i<32*192;i+=256){int pi=i/192,c=i-pi*192; tile[pi][c]=g_conv[((size_t)(b*1024+p0+pi))*192+c];}
    __syncthreads();
    for(int i=tid;i<192*32;i+=256){
        int c=i>>5,pi=i&31;
        float v=tile[pi][c]*g_bna[c]+g_bnb[c];
        out[((size_t)b*192+c)*1024+p0+pi]=(v>=0.f)?v:0.01f*v;
    }
}

extern "C" void kernel_launch(void* const* d_in,const int* in_sizes,int n_in,void* d_out,int out_size){
    const float* x=(const float*)d_in[0];
    const float* ln_w=(const float*)d_in[1];
    const float* ln_b=(const float*)d_in[2];
    const float* w_up=(const float*)d_in[3];
    const float* b_up=(const float*)d_in[4];
    const float* conv_k=(const float*)d_in[5];
    const float* conv_b=(const float*)d_in[6];
    const float* w_q=(const float*)d_in[7];
    const float* w_k=(const float*)d_in[8];
    const float* w_i=(const float*)d_in[9];
    const float* b_i=(const float*)d_in[10];
    const float* w_f=(const float*)d_in[11];
    const float* b_f=(const float*)d_in[12];
    const float* skip=(const float*)d_in[13];
    const float* mh_w=(const float*)d_in[14];
    const float* mh_b=(const float*)d_in[15];
    const float* w_down=(const float*)d_in[16];
    const float* b_down=(const float*)d_in[17];
    const float* w_lin=(const float*)d_in[18];
    const float* b_lin=(const float*)d_in[19];
    const float* conv2w=(const float*)d_in[20];
    const float* bn_g=(const float*)d_in[22];
    const float* bn_b=(const float*)d_in[23];
    float* out=(float*)d_out;

    float *p_hln,*p_up,*p_xact,*p_qk,*p_hout,*p_seq,*p_t1,*p_y,*p_wqk,*p_wcomb,*p_gates,*p_wconv,*p_conv;
    cudaGetSymbolAddress((void**)&p_hln,g_hln);
    cudaGetSymbolAddress((void**)&p_up,g_up);
    cudaGetSymbolAddress((void**)&p_xact,g_xact);
    cudaGetSymbolAddress((void**)&p_qk,g_qk);
    cudaGetSymbolAddress((void**)&p_hout,g_hout);
    cudaGetSymbolAddress((void**)&p_seq,g_seq);
    cudaGetSymbolAddress((void**)&p_t1,g_t1);
    cudaGetSymbolAddress((void**)&p_y,g_y);
    cudaGetSymbolAddress((void**)&p_wqk,g_wqk);
    cudaGetSymbolAddress((void**)&p_wcomb,g_wcomb);
    cudaGetSymbolAddress((void**)&p_gates,g_gates);
    cudaGetSymbolAddress((void**)&p_wconv,g_wconv);
    cudaGetSymbolAddress((void**)&p_conv,g_conv);

    prep_gates_kernel<<<1152,256>>>(w_q,w_k,w_i,w_f);
    prep_gates2_kernel<<<192,256>>>(w_i,w_f,b_i,b_f);
    prep_wqk_kernel<<<1152,256>>>(w_q,w_k);
    prep_wconv_kernel<<<1296,256>>>(conv2w);
    transpose_ln_kernel<<<512,256>>>(x,ln_w,ln_b);
    tgemm<0,0><<<dim3(12,128),256>>>(p_hln,w_up,p_up,192,192,768,768,b_up);
    conv1d_kernel<<<NROWS,384>>>(conv_k,conv_b);
    tgemm<0,0><<<dim3(12,128),256>>>(p_xact,p_wqk,p_qk,384,384,768,768,nullptr);
    tgemm<1,2><<<dim3(1,128),256>>>(nullptr,p_wcomb,p_gates,768,0,64,64,nullptr);
    scan_kernel<<<BB*NHD,128>>>(skip,mh_w,mh_b);
    tgemm<0,0><<<dim3(3,128),256>>>(p_hout,w_down,p_t1,384,384,192,192,b_down);
    tgemm<0,3><<<dim3(3,128),256>>>(p_seq,w_lin,p_y,192,192,192,192,b_lin);
    tgemm<2,0><<<dim3(3,128),256>>>(nullptr,p_wconv,p_conv,1728,0,192,192,nullptr);
    bn_stats_kernel<<<256,192>>>();
    bn_reduce_kernel<<<1,192>>>(bn_g,bn_b);
    out_bn_kernel<<<512,256>>>(out);
}

// round 15
// speedup vs baseline: 1.3826x; 1.3826x over previous
#include <cuda_runtime.h>
#include <math.h>
#define BB 16
#define CC 192
#define SS 1024
#define NI 384
#define NHD 12
#define DHD 32
#define NROWS (BB*SS)

__device__ float g_seq[NROWS*CC], g_hln[NROWS*CC], g_up[NROWS*768], g_xact[NROWS*NI];
__device__ float g_qk[NROWS*768], g_gates[NROWS*64], g_hout[NROWS*NI];
__device__ float g_t1[NROWS*CC], g_y[NROWS*CC], g_conv[NROWS*CC];
__device__ float g_wcomb[768*64], g_gbias[64], g_wconv[1728*CC], g_wqk[384*768];
__device__ float g_bnpart[256*2*CC], g_bna[CC], g_bnb[CC];

__device__ __forceinline__ float logsigf(float v){return (v>=0.f)?-log1pf(expf(-v)):v-log1pf(expf(v));}
__device__ __forceinline__ float siluf(float v){return v/(1.f+__expf(-v));}
__device__ __forceinline__ void cpa16(void* s,const void* g,bool p){
    unsigned sa=(unsigned)__cvta_generic_to_shared(s);
    int sz=p?16:0;
    asm volatile("cp.async.cg.shared.global [%0],[%1],16,%2;"::"r"(sa),"l"(g),"r"(sz));
}
#define CPA_COMMIT asm volatile("cp.async.commit_group;")
#define CPA_WAIT1  asm volatile("cp.async.wait_group 1;")
#define CPA_WAIT0  asm volatile("cp.async.wait_group 0;")

__global__ void prep_gates_kernel(const float* wq,const float* wk,const float* wi,const float* wf){
    int gid=blockIdx.x*8+(threadIdx.x>>5);
    int lane=threadIdx.x&31;
    int r=gid%384, c=gid/384;
    const float* W=(c<12)?wi:wf; int cc=(c<12)?c:c-12;
    float s=0.f;
    for(int j=lane;j<384;j+=32)
        s+=wq[r*384+j]*W[j*12+cc]+wk[r*384+j]*W[(384+j)*12+cc];
#pragma unroll
    for(int o=16;o>0;o>>=1) s+=__shfl_xor_sync(~0u,s,o);
    if(lane==0) g_wcomb[r*64+c]=s;
}
__global__ void prep_gates2_kernel(const float* wi,const float* wf,const float* bi,const float* bf){
    int idx=blockIdx.x*256+threadIdx.x;
    if(idx<64) g_gbias[idx]=(idx<12)?bi[idx]:(idx<24?bf[idx-12]:0.f);
    if(idx>=768*64) return;
    int r=idx>>6,c=idx&63;
    if(r<384&&c<24) return;
    float v=0.f;
    if(c<24&&r>=384){
        const float* W=(c<12)?wi:wf; int cc=(c<12)?c:c-12;
        v=W[(768+(r-384))*12+cc];
    }
    g_wcomb[idx]=v;
}

__global__ void prep_wqk_kernel(const float* wq,const float* wk){
    int idx=blockIdx.x*256+threadIdx.x;
    if(idx>=384*768) return;
    int k=idx/768,n=idx-k*768;
    g_wqk[idx]=(n<384)?wq[k*384+n]:wk[k*384+(n-384)];
}

__global__ void prep_wconv_kernel(const float* w){
    int idx=blockIdx.x*256+threadIdx.x;
    if(idx>=192*1728) return;
    int co=idx/1728,rem=idx-co*1728,ci=rem/9,tap=rem-ci*9;
    g_wconv[(tap*192+ci)*192+co]=w[idx];
}

__global__ void transpose_ln_kernel(const float* x,const float* lnw,const float* lnb){
    __shared__ float tile[CC][33];
    int b=blockIdx.x>>5,s0=(blockIdx.x&31)*32,tid=threadIdx.x;
    for(int i=tid;i<CC*32;i+=256){int c=i>>5,si=i&31; tile[c][si]=x[((size_t)b*CC+c)*SS+s0+si];}
    __syncthreads();
    int warp=tid>>5,lane=tid&31;
    for(int t=0;t<4;t++){
        int si=warp*4+t; float v[6],sum=0.f,sq=0.f;
#pragma unroll
        for(int u=0;u<6;u++){v[u]=tile[lane+32*u][si];sum+=v[u];sq+=v[u]*v[u];}
#pragma unroll
        for(int o=16;o>0;o>>=1){sum+=__shfl_xor_sync(~0u,sum,o);sq+=__shfl_xor_sync(~0u,sq,o);}
        float mu=sum*(1.f/192.f),var=sq*(1.f/192.f)-mu*mu,rstd=rsqrtf(var+1e-5f);
        size_t row=(size_t)b*SS+s0+si;
#pragma unroll
        for(int u=0;u<6;u++){int c=lane+32*u; g_seq[row*CC+c]=v[u]; g_hln[row*CC+c]=(v[u]-mu)*rstd*lnw[c]+lnb[c];}
    }
}

// ---- TF32 MMA GEMM, 3-stage cp.async pipeline (tail drained).
// SRC:0 plain,1 gates-concat,2 conv2-gather. ACT:0 none,1 silu,2 gates,3 silu+seq+t1->y ----
template<int SRC,int ACT>
__global__ void __launch_bounds__(256) tgemm(const float* A,const float* B,float* Cp,int K,int lda,int ldb,int ldc,const float* bias){
    __shared__ float As[3][128][20];
    __shared__ float Bs[3][16][72];
    int tid=threadIdx.x,lane=tid&31,wrp=tid>>5;
    int wm=wrp&3,wn=wrp>>2;
    int bm=blockIdx.y*128,bn=blockIdx.x*64;
    int g=lane>>2,tg=lane&3;
    float acc[2][4][4]={};
    int T=K/16;

    int idA0=tid*2,rA0=idA0>>2,kqA0=(idA0&3)<<2;
    int idA1=tid*2+1,rA1=idA1>>2,kqA1=(idA1&3)<<2;
    int krB=tid>>4,nqB=(tid&15)<<2;

#define LOADTILE(t,buf) { \
        int k0=(t)*16; \
        const float *sa0,*sa1; bool p0=true,p1=true; \
        if(SRC==0){ \
            sa0=A+(size_t)(bm+rA0)*lda+k0+kqA0; \
            sa1=A+(size_t)(bm+rA1)*lda+k0+kqA1; \
        } else if(SRC==1){ \
            int ka=k0+kqA0,kb=k0+kqA1; \
            sa0=(ka<384)?(g_xact+(size_t)(bm+rA0)*384+ka):(g_up+(size_t)(bm+rA0)*768+(ka-384)); \
            sa1=(kb<384)?(g_xact+(size_t)(bm+rA1)*384+kb):(g_up+(size_t)(bm+rA1)*768+(kb-384)); \
        } else { \
            int tap=k0/192,rem=k0-tap*192; \
            int dh=tap/3-1,dw=tap-(tap/3)*3-1,off=dh*32+dw; \
            int row0=bm+rA0,pp0=row0&1023,hh0=(pp0>>5)+dh,ww0=(pp0&31)+dw; \
            int row1=bm+rA1,pp1=row1&1023,hh1=(pp1>>5)+dh,ww1=(pp1&31)+dw; \
            p0=((unsigned)hh0<32u&&(unsigned)ww0<32u); \
            p1=((unsigned)hh1<32u&&(unsigned)ww1<32u); \
            sa0=p0?(g_y+(size_t)(row0+off)*192+rem+kqA0):g_y; \
            sa1=p1?(g_y+(size_t)(row1+off)*192+rem+kqA1):g_y; \
        } \
        cpa16(&As[buf][rA0][kqA0],sa0,p0); \
        cpa16(&As[buf][rA1][kqA1],sa1,p1); \
        cpa16(&Bs[buf][krB][nqB],B+(size_t)(k0+krB)*ldb+bn+nqB,true); \
        CPA_COMMIT; }

    LOADTILE(0,0);
    LOADTILE(1,1);
    for(int t=0;t<T;t++){
        if(t+2<T){ CPA_WAIT1; } else { CPA_WAIT0; }
        __syncthreads();
        if(t+2<T){ int nb=(t+2)%3; LOADTILE(t+2,nb); }
        int buf=t%3;
#pragma unroll
        for(int kk=0;kk<16;kk+=8){
            unsigned a[2][4],b[4][2];
#pragma unroll
            for(int mt=0;mt<2;mt++){
                int m0=wm*32+mt*16;
                a[mt][0]=__float_as_uint(As[buf][m0+g  ][kk+tg  ]);
                a[mt][1]=__float_as_uint(As[buf][m0+g+8][kk+tg  ]);
                a[mt][2]=__float_as_uint(As[buf][m0+g  ][kk+tg+4]);
                a[mt][3]=__float_as_uint(As[buf][m0+g+8][kk+tg+4]);
            }
#pragma unroll
            for(int nt=0;nt<4;nt++){
                int n0=wn*32+nt*8;
                b[nt][0]=__float_as_uint(Bs[buf][kk+tg  ][n0+g]);
                b[nt][1]=__float_as_uint(Bs[buf][kk+tg+4][n0+g]);
            }
#pragma unroll
            for(int mt=0;mt<2;mt++)
#pragma unroll
                for(int nt=0;nt<4;nt++)
                    asm volatile("mma.sync.aligned.m16n8k8.row.col.f32.tf32.tf32.f32 {%0,%1,%2,%3},{%4,%5,%6,%7},{%8,%9},{%0,%1,%2,%3};"
                        : "+f"(acc[mt][nt][0]),"+f"(acc[mt][nt][1]),"+f"(acc[mt][nt][2]),"+f"(acc[mt][nt][3])
                        : "r"(a[mt][0]),"r"(a[mt][1]),"r"(a[mt][2]),"r"(a[mt][3]),"r"(b[nt][0]),"r"(b[nt][1]));
        }
    }
#undef LOADTILE
#pragma unroll
    for(int mt=0;mt<2;mt++){
        int r1=bm+wm*32+mt*16+g;
#pragma unroll
        for(int nt=0;nt<4;nt++){
            int cb=bn+wn*32+nt*8+2*tg;
            float v[4]={acc[mt][nt][0],acc[mt][nt][1],acc[mt][nt][2],acc[mt][nt][3]};
            size_t ro0=(size_t)r1*ldc+cb, ro1=(size_t)(r1+8)*ldc+cb;
            if(ACT==2){
                v[0]+=g_gbias[cb]; v[1]+=g_gbias[cb+1]; v[2]+=g_gbias[cb]; v[3]+=g_gbias[cb+1];
                if(cb>=12&&cb<24){v[0]=logsigf(v[0]);v[2]=logsigf(v[2]);}
                if(cb+1>=12&&cb+1<24){v[1]=logsigf(v[1]);v[3]=logsigf(v[3]);}
            } else {
                if(bias){float b0=bias[cb],b1=bias[cb+1];v[0]+=b0;v[1]+=b1;v[2]+=b0;v[3]+=b1;}
                if(ACT==1){v[0]=siluf(v[0]);v[1]=siluf(v[1]);v[2]=siluf(v[2]);v[3]=siluf(v[3]);}
                if(ACT==3){
                    v[0]=siluf(v[0])+g_seq[ro0]+g_t1[ro0];     v[1]=siluf(v[1])+g_seq[ro0+1]+g_t1[ro0+1];
                    v[2]=siluf(v[2])+g_seq[ro1]+g_t1[ro1];     v[3]=siluf(v[3])+g_seq[ro1+1]+g_t1[ro1+1];
                }
            }
            *(float2*)(Cp+ro0)=make_float2(v[0],v[1]);
            *(float2*)(Cp+ro1)=make_float2(v[2],v[3]);
        }
    }
}

__global__ void conv1d_kernel(const float* ck,const float* cb){
    int row=blockIdx.x,i=threadIdx.x,s=row&1023;
    float acc=cb[i];
    const float* base=g_up+(size_t)row*768+i;
#pragma unroll
    for(int t=0;t<4;t++){int sp=s-3+t; if(sp>=0)acc=fmaf(base[(t-3)*768],ck[i*4+t],acc);}
    g_xact[(size_t)row*NI+i]=siluf(acc);
}

// ---- scan: warp0 computes; prev-step shfl ladder issued BEFORE the FMA loop (latency hidden),
// finalized after. warps1-3 prefetch tiles. ----
#define TT 32
__device__ __forceinline__ void scan_load_tile(int tile,int buf,int lt,int nth,
    size_t r0,int head,float ksc,
    float (*sQ)[TT][DHD],float (*sK)[TT][DHD],float (*sV)[TT][DHD],
    float (*sZ)[TT][DHD],float (*sX)[TT][DHD],float (*sI)[TT],float (*sF)[TT])
{
    size_t base=(r0+(size_t)tile*TT);
    for(int u=lt;u<1280;u+=nth){
        int arr=u>>8,rem=u&255,step=rem>>3,l4=(rem&7)<<2;
        size_t row=base+step;
        float4 v;
        if(arr==0)      v=*(const float4*)(g_qk  +row*768+     head*DHD+l4);
        else if(arr==1){v=*(const float4*)(g_qk  +row*768+384+ head*DHD+l4);
                        v.x*=ksc;v.y*=ksc;v.z*=ksc;v.w*=ksc;}
        else if(arr==2) v=*(const float4*)(g_up  +row*768+     head*DHD+l4);
        else if(arr==3) v=*(const float4*)(g_up  +row*768+384+ head*DHD+l4);
        else            v=*(const float4*)(g_xact+row*384+     head*DHD+l4);
        float* dst=(arr==0)?&sQ[buf][step][l4]:(arr==1)?&sK[buf][step][l4]:
                   (arr==2)?&sV[buf][step][l4]:(arr==3)?&sZ[buf][step][l4]:&sX[buf][step][l4];
        *(float4*)dst=v;
    }
    for(int u=lt;u<2*TT;u+=nth){
        int step=u>>1;
        size_t row=base+step;
        if(u&1) sF[buf][step]=g_gates[row*64+12+head];
        else    sI[buf][step]=g_gates[row*64+head];
    }
}

__global__ void __launch_bounds__(128) scan_kernel(const float* skip,const float* mhw,const float* mhb){
    const int tid=threadIdx.x,lane=tid&31,wid=tid>>5;
    const int bh=blockIdx.x,b=bh/NHD,head=bh-b*NHD,idx=head*DHD+lane;
    __shared__ float sQ[2][TT][DHD],sK[2][TT][DHD],sV[2][TT][DHD],sZ[2][TT][DHD],sX[2][TT][DHD];
    __shared__ float sI[2][TT],sF[2][TT];
    const float ksc=0.17677669529663687f;
    const size_t r0=(size_t)b*SS;

    scan_load_tile(0,0,tid,128,r0,head,ksc,sQ,sK,sV,sZ,sX,sI,sF);
    __syncthreads();

    float C[DHD];
#pragma unroll
    for(int e=0;e<DHD;e++)C[e]=0.f;
    float nl=0.f,m=0.f;
    const float wg=mhw[idx],bg=mhb[idx],skp=skip[idx];

    float pNQ=0.f,pH=0.f,pZ=0.f,pX=0.f;
    size_t pRow=0; int hasp=0;

    const int NTILE=SS/TT;
    for(int tile=0;tile<NTILE;tile++){
        int buf=tile&1;
        if(wid>0){
            if(tile+1<NTILE) scan_load_tile(tile+1,buf^1,tid-32,96,r0,head,ksc,sQ,sK,sV,sZ,sX,sI,sF);
        } else {
            for(int t=0;t<TT;t++){
                float cq=sQ[buf][t][lane],ckk=sK[buf][t][lane],cv=sV[buf][t][lane];
                float cz=sZ[buf][t][lane],cx=sX[buf][t][lane];
                float ci=sI[buf][t],cf=sF[buf][t];
                float mnew=fmaxf(cf+m,ci);
                float fs=__expf(cf+m-mnew),is=__expf(ci-mnew);
                m=mnew;
                nl=fs*nl+is*ckk;
                float isv=is*cv;
                // issue previous step's reduction ladder now; latency drains under the FMA loop
                float rq=pNQ,rs=pH,rr=pH*pH;
                if(hasp){
#pragma unroll
                    for(int o=16;o>0;o>>=1){
                        rq+=__shfl_xor_sync(~0u,rq,o);
                        rs+=__shfl_xor_sync(~0u,rs,o);
                        rr+=__shfl_xor_sync(~0u,rr,o);
                    }
                }
                float h0=0.f,h1=0.f,h2=0.f,h3=0.f;
#pragma unroll
                for(int j=0;j<8;j++){
                    float4 k4=*(const float4*)(&sK[buf][t][4*j]),q4=*(const float4*)(&sQ[buf][t][4*j]);
                    C[4*j]  =fmaf(isv,k4.x,fs*C[4*j]);   h0=fmaf(C[4*j],  q4.x,h0);
                    C[4*j+1]=fmaf(isv,k4.y,fs*C[4*j+1]); h1=fmaf(C[4*j+1],q4.y,h1);
                    C[4*j+2]=fmaf(isv,k4.z,fs*C[4*j+2]); h2=fmaf(C[4*j+2],q4.z,h2);
                    C[4*j+3]=fmaf(isv,k4.w,fs*C[4*j+3]); h3=fmaf(C[4*j+3],q4.w,h3);
                }
                float h=(h0+h1)+(h2+h3);
                float nqcur=nl*cq;
                if(hasp){
                    float d=fmaxf(fabsf(rq),1.f);
                    float mu=rs*(1.f/32.f),var=rr*(1.f/32.f)-mu*mu;
                    float rstd=rsqrtf(var+1e-5f*d*d);
                    float hn=(pH-mu)*rstd*wg+bg;
                    g_hout[pRow]=(hn+skp*pX)*siluf(pZ);
                }
                pNQ=nqcur; pH=h; pZ=cz; pX=cx; pRow=(r0+(size_t)tile*TT+t)*NI+idx; hasp=1;
            }
        }
        __syncthreads();
    }
    if(wid==0&&hasp){
        float rq=pNQ,rs=pH,rr=pH*pH;
#pragma unroll
        for(int o=16;o>0;o>>=1){
            rq+=__shfl_xor_sync(~0u,rq,o);
            rs+=__shfl_xor_sync(~0u,rs,o);
            rr+=__shfl_xor_sync(~0u,rr,o);
        }
        float d=fmaxf(fabsf(rq),1.f);
        float mu=rs*(1.f/32.f),var=rr*(1.f/32.f)-mu*mu;
        float rstd=rsqrtf(var+1e-5f*d*d);
        float hn=(pH-mu)*rstd*wg+bg;
        g_hout[pRow]=(hn+skp*pX)*siluf(pZ);
    }
}

__global__ void bn_stats_kernel(){
    int c=threadIdx.x,blk=blockIdx.x;
    float s=0.f,q=0.f;
    for(int r=0;r<64;r++){float v=g_conv[((size_t)(blk*64+r))*192+c]; s+=v; q+=v*v;}
    g_bnpart[blk*384+c]=s; g_bnpart[blk*384+192+c]=q;
}
__global__ void bn_reduce_kernel(const float* bng,const float* bnb){
    int c=threadIdx.x;
    float s=0.f,q=0.f;
    for(int b=0;b<256;b++){s+=g_bnpart[b*384+c];q+=g_bnpart[b*384+192+c];}
    float mu=s*(1.f/16384.f),var=q*(1.f/16384.f)-mu*mu;
    float a=bng[c]*rsqrtf(var+1e-5f);
    g_bna[c]=a; g_bnb[c]=bnb[c]-mu*a;
}

__global__ void out_bn_kernel(float* out){
    __shared__ float tile[32][193];
    int b=blockIdx.x>>5,p0=(blockIdx.x&31)*32,tid=threadIdx.x;
    for(int i=tid;i<32*192;i+=256){int pi=i/192,c=i-pi*192; tile[pi][c]=g_conv[((size_t)(b*1024+p0+pi))*192+c];}
    __syncthreads();
    for(int i=tid;i<192*32;i+=256){
        int c=i>>5,pi=i&31;
        float v=tile[pi][c]*g_bna[c]+g_bnb[c];
        out[((size_t)b*192+c)*1024+p0+pi]=(v>=0.f)?v:0.01f*v;
    }
}

extern "C" void kernel_launch(void* const* d_in,const int* in_sizes,int n_in,void* d_out,int out_size){
    const float* x=(const float*)d_in[0];
    const float* ln_w=(const float*)d_in[1];
    const float* ln_b=(const float*)d_in[2];
    const float* w_up=(const float*)d_in[3];
    const float* b_up=(const float*)d_in[4];
    const float* conv_k=(const float*)d_in[5];
    const float* conv_b=(const float*)d_in[6];
    const float* w_q=(const float*)d_in[7];
    const float* w_k=(const float*)d_in[8];
    const float* w_i=(const float*)d_in[9];
    const float* b_i=(const float*)d_in[10];
    const float* w_f=(const float*)d_in[11];
    const float* b_f=(const float*)d_in[12];
    const float* skip=(const float*)d_in[13];
    const float* mh_w=(const float*)d_in[14];
    const float* mh_b=(const float*)d_in[15];
    const float* w_down=(const float*)d_in[16];
    const float* b_down=(const float*)d_in[17];
    const float* w_lin=(const float*)d_in[18];
    const float* b_lin=(const float*)d_in[19];
    const float* conv2w=(const float*)d_in[20];
    const float* bn_g=(const float*)d_in[22];
    const float* bn_b=(const float*)d_in[23];
    float* out=(float*)d_out;

    float *p_hln,*p_up,*p_xact,*p_qk,*p_hout,*p_seq,*p_t1,*p_y,*p_wqk,*p_wcomb,*p_gates,*p_wconv,*p_conv;
    cudaGetSymbolAddress((void**)&p_hln,g_hln);
    cudaGetSymbolAddress((void**)&p_up,g_up);
    cudaGetSymbolAddress((void**)&p_xact,g_xact);
    cudaGetSymbolAddress((void**)&p_qk,g_qk);
    cudaGetSymbolAddress((void**)&p_hout,g_hout);
    cudaGetSymbolAddress((void**)&p_seq,g_seq);
    cudaGetSymbolAddress((void**)&p_t1,g_t1);
    cudaGetSymbolAddress((void**)&p_y,g_y);
    cudaGetSymbolAddress((void**)&p_wqk,g_wqk);
    cudaGetSymbolAddress((void**)&p_wcomb,g_wcomb);
    cudaGetSymbolAddress((void**)&p_gates,g_gates);
    cudaGetSymbolAddress((void**)&p_wconv,g_wconv);
    cudaGetSymbolAddress((void**)&p_conv,g_conv);

    prep_gates_kernel<<<1152,256>>>(w_q,w_k,w_i,w_f);
    prep_gates2_kernel<<<192,256>>>(w_i,w_f,b_i,b_f);
    prep_wqk_kernel<<<1152,256>>>(w_q,w_k);
    prep_wconv_kernel<<<1296,256>>>(conv2w);
    transpose_ln_kernel<<<512,256>>>(x,ln_w,ln_b);
    tgemm<0,0><<<dim3(12,128),256>>>(p_hln,w_up,p_up,192,192,768,768,b_up);
    conv1d_kernel<<<NROWS,384>>>(conv_k,conv_b);
    tgemm<0,0><<<dim3(12,128),256>>>(p_xact,p_wqk,p_qk,384,384,768,768,nullptr);
    tgemm<1,2><<<dim3(1,128),256>>>(nullptr,p_wcomb,p_gates,768,0,64,64,nullptr);
    scan_kernel<<<BB*NHD,128>>>(skip,mh_w,mh_b);
    tgemm<0,0><<<dim3(3,128),256>>>(p_hout,w_down,p_t1,384,384,192,192,b_down);
    tgemm<0,3><<<dim3(3,128),256>>>(p_seq,w_lin,p_y,192,192,192,192,b_lin);
    tgemm<2,0><<<dim3(3,128),256>>>(nullptr,p_wconv,p_conv,1728,0,192,192,nullptr);
    bn_stats_kernel<<<256,192>>>();
    bn_reduce_kernel<<<1,192>>>(bn_g,bn_b);
    out_bn_kernel<<<512,256>>>(out);
}

// round 17
// speedup vs baseline: 1.4593x; 1.0555x over previous
#include <cuda_runtime.h>
#include <math.h>
#define BB 16
#define CC 192
#define SS 1024
#define NI 384
#define NHD 12
#define DHD 32
#define NROWS (BB*SS)

__device__ float g_seq[NROWS*CC], g_hln[NROWS*CC], g_up[NROWS*768], g_xact[NROWS*NI];
__device__ float g_qk[NROWS*768], g_gates[NROWS*64], g_hout[NROWS*NI];
__device__ float g_t1[NROWS*CC], g_y[NROWS*CC], g_conv[NROWS*CC];
__device__ float g_wcomb[768*64], g_gbias[64], g_wconv[1728*CC], g_wqk[384*768];
__device__ float g_bnpart[256*2*CC], g_bna[CC], g_bnb[CC];
__device__ float g_scr[NI];

__device__ __forceinline__ float logsigf(float v){return (v>=0.f)?-log1pf(expf(-v)):v-log1pf(expf(v));}
__device__ __forceinline__ float siluf(float v){return v/(1.f+__expf(-v));}
__device__ __forceinline__ void cpa16(void* s,const void* g,bool p){
    unsigned sa=(unsigned)__cvta_generic_to_shared(s);
    int sz=p?16:0;
    asm volatile("cp.async.cg.shared.global [%0],[%1],16,%2;"::"r"(sa),"l"(g),"r"(sz));
}
#define CPA_COMMIT asm volatile("cp.async.commit_group;")
#define CPA_WAIT1  asm volatile("cp.async.wait_group 1;")
#define CPA_WAIT0  asm volatile("cp.async.wait_group 0;")

__global__ void prep_gates_kernel(const float* wq,const float* wk,const float* wi,const float* wf){
    int gid=blockIdx.x*8+(threadIdx.x>>5);
    int lane=threadIdx.x&31;
    int r=gid%384, c=gid/384;
    const float* W=(c<12)?wi:wf; int cc=(c<12)?c:c-12;
    float s=0.f;
    for(int j=lane;j<384;j+=32)
        s+=wq[r*384+j]*W[j*12+cc]+wk[r*384+j]*W[(384+j)*12+cc];
#pragma unroll
    for(int o=16;o>0;o>>=1) s+=__shfl_xor_sync(~0u,s,o);
    if(lane==0) g_wcomb[r*64+c]=s;
}
__global__ void prep_gates2_kernel(const float* wi,const float* wf,const float* bi,const float* bf){
    int idx=blockIdx.x*256+threadIdx.x;
    if(idx<64) g_gbias[idx]=(idx<12)?bi[idx]:(idx<24?bf[idx-12]:0.f);
    if(idx>=768*64) return;
    int r=idx>>6,c=idx&63;
    if(r<384&&c<24) return;
    float v=0.f;
    if(c<24&&r>=384){
        const float* W=(c<12)?wi:wf; int cc=(c<12)?c:c-12;
        v=W[(768+(r-384))*12+cc];
    }
    g_wcomb[idx]=v;
}

__global__ void prep_wqk_kernel(const float* wq,const float* wk){
    int idx=blockIdx.x*256+threadIdx.x;
    if(idx>=384*768) return;
    int k=idx/768,n=idx-k*768;
    g_wqk[idx]=(n<384)?wq[k*384+n]:wk[k*384+(n-384)];
}

__global__ void prep_wconv_kernel(const float* w){
    int idx=blockIdx.x*256+threadIdx.x;
    if(idx>=192*1728) return;
    int co=idx/1728,rem=idx-co*1728,ci=rem/9,tap=rem-ci*9;
    g_wconv[(tap*192+ci)*192+co]=w[idx];
}

__global__ void transpose_ln_kernel(const float* x,const float* lnw,const float* lnb){
    __shared__ float tile[CC][33];
    int b=blockIdx.x>>5,s0=(blockIdx.x&31)*32,tid=threadIdx.x;
    for(int i=tid;i<CC*32;i+=256){int c=i>>5,si=i&31; tile[c][si]=x[((size_t)b*CC+c)*SS+s0+si];}
    __syncthreads();
    int warp=tid>>5,lane=tid&31;
    for(int t=0;t<4;t++){
        int si=warp*4+t; float v[6],sum=0.f,sq=0.f;
#pragma unroll
        for(int u=0;u<6;u++){v[u]=tile[lane+32*u][si];sum+=v[u];sq+=v[u]*v[u];}
#pragma unroll
        for(int o=16;o>0;o>>=1){sum+=__shfl_xor_sync(~0u,sum,o);sq+=__shfl_xor_sync(~0u,sq,o);}
        float mu=sum*(1.f/192.f),var=sq*(1.f/192.f)-mu*mu,rstd=rsqrtf(var+1e-5f);
        size_t row=(size_t)b*SS+s0+si;
#pragma unroll
        for(int u=0;u<6;u++){int c=lane+32*u; g_seq[row*CC+c]=v[u]; g_hln[row*CC+c]=(v[u]-mu)*rstd*lnw[c]+lnb[c];}
    }
}

// ---- TF32 MMA GEMM, 3-stage cp.async pipeline (tail drained).
// SRC:0 plain,1 gates-concat,2 conv2-gather. ACT:0 none,1 silu,2 gates,3 silu+seq+t1->y ----
template<int SRC,int ACT>
__global__ void __launch_bounds__(256) tgemm(const float* A,const float* B,float* Cp,int K,int lda,int ldb,int ldc,const float* bias){
    __shared__ float As[3][128][20];
    __shared__ float Bs[3][16][72];
    int tid=threadIdx.x,lane=tid&31,wrp=tid>>5;
    int wm=wrp&3,wn=wrp>>2;
    int bm=blockIdx.y*128,bn=blockIdx.x*64;
    int g=lane>>2,tg=lane&3;
    float acc[2][4][4]={};
    int T=K/16;

    int idA0=tid*2,rA0=idA0>>2,kqA0=(idA0&3)<<2;
    int idA1=tid*2+1,rA1=idA1>>2,kqA1=(idA1&3)<<2;
    int krB=tid>>4,nqB=(tid&15)<<2;

#define LOADTILE(t,buf) { \
        int k0=(t)*16; \
        const float *sa0,*sa1; bool p0=true,p1=true; \
        if(SRC==0){ \
            sa0=A+(size_t)(bm+rA0)*lda+k0+kqA0; \
            sa1=A+(size_t)(bm+rA1)*lda+k0+kqA1; \
        } else if(SRC==1){ \
            int ka=k0+kqA0,kb=k0+kqA1; \
            sa0=(ka<384)?(g_xact+(size_t)(bm+rA0)*384+ka):(g_up+(size_t)(bm+rA0)*768+(ka-384)); \
            sa1=(kb<384)?(g_xact+(size_t)(bm+rA1)*384+kb):(g_up+(size_t)(bm+rA1)*768+(kb-384)); \
        } else { \
            int tap=k0/192,rem=k0-tap*192; \
            int dh=tap/3-1,dw=tap-(tap/3)*3-1,off=dh*32+dw; \
            int row0=bm+rA0,pp0=row0&1023,hh0=(pp0>>5)+dh,ww0=(pp0&31)+dw; \
            int row1=bm+rA1,pp1=row1&1023,hh1=(pp1>>5)+dh,ww1=(pp1&31)+dw; \
            p0=((unsigned)hh0<32u&&(unsigned)ww0<32u); \
            p1=((unsigned)hh1<32u&&(unsigned)ww1<32u); \
            sa0=p0?(g_y+(size_t)(row0+off)*192+rem+kqA0):g_y; \
            sa1=p1?(g_y+(size_t)(row1+off)*192+rem+kqA1):g_y; \
        } \
        cpa16(&As[buf][rA0][kqA0],sa0,p0); \
        cpa16(&As[buf][rA1][kqA1],sa1,p1); \
        cpa16(&Bs[buf][krB][nqB],B+(size_t)(k0+krB)*ldb+bn+nqB,true); \
        CPA_COMMIT; }

    LOADTILE(0,0);
    LOADTILE(1,1);
    for(int t=0;t<T;t++){
        if(t+2<T){ CPA_WAIT1; } else { CPA_WAIT0; }
        __syncthreads();
        if(t+2<T){ int nb=(t+2)%3; LOADTILE(t+2,nb); }
        int buf=t%3;
#pragma unroll
        for(int kk=0;kk<16;kk+=8){
            unsigned a[2][4],b[4][2];
#pragma unroll
            for(int mt=0;mt<2;mt++){
                int m0=wm*32+mt*16;
                a[mt][0]=__float_as_uint(As[buf][m0+g  ][kk+tg  ]);
                a[mt][1]=__float_as_uint(As[buf][m0+g+8][kk+tg  ]);
                a[mt][2]=__float_as_uint(As[buf][m0+g  ][kk+tg+4]);
                a[mt][3]=__float_as_uint(As[buf][m0+g+8][kk+tg+4]);
            }
#pragma unroll
            for(int nt=0;nt<4;nt++){
                int n0=wn*32+nt*8;
                b[nt][0]=__float_as_uint(Bs[buf][kk+tg  ][n0+g]);
                b[nt][1]=__float_as_uint(Bs[buf][kk+tg+4][n0+g]);
            }
#pragma unroll
            for(int mt=0;mt<2;mt++)
#pragma unroll
                for(int nt=0;nt<4;nt++)
                    asm volatile("mma.sync.aligned.m16n8k8.row.col.f32.tf32.tf32.f32 {%0,%1,%2,%3},{%4,%5,%6,%7},{%8,%9},{%0,%1,%2,%3};"
                        : "+f"(acc[mt][nt][0]),"+f"(acc[mt][nt][1]),"+f"(acc[mt][nt][2]),"+f"(acc[mt][nt][3])
                        : "r"(a[mt][0]),"r"(a[mt][1]),"r"(a[mt][2]),"r"(a[mt][3]),"r"(b[nt][0]),"r"(b[nt][1]));
        }
    }
#undef LOADTILE
#pragma unroll
    for(int mt=0;mt<2;mt++){
        int r1=bm+wm*32+mt*16+g;
#pragma unroll
        for(int nt=0;nt<4;nt++){
            int cb=bn+wn*32+nt*8+2*tg;
            float v[4]={acc[mt][nt][0],acc[mt][nt][1],acc[mt][nt][2],acc[mt][nt][3]};
            size_t ro0=(size_t)r1*ldc+cb, ro1=(size_t)(r1+8)*ldc+cb;
            if(ACT==2){
                v[0]+=g_gbias[cb]; v[1]+=g_gbias[cb+1]; v[2]+=g_gbias[cb]; v[3]+=g_gbias[cb+1];
                if(cb>=12&&cb<24){v[0]=logsigf(v[0]);v[2]=logsigf(v[2]);}
                if(cb+1>=12&&cb+1<24){v[1]=logsigf(v[1]);v[3]=logsigf(v[3]);}
            } else {
                if(bias){float b0=bias[cb],b1=bias[cb+1];v[0]+=b0;v[1]+=b1;v[2]+=b0;v[3]+=b1;}
                if(ACT==1){v[0]=siluf(v[0]);v[1]=siluf(v[1]);v[2]=siluf(v[2]);v[3]=siluf(v[3]);}
                if(ACT==3){
                    v[0]=siluf(v[0])+g_seq[ro0]+g_t1[ro0];     v[1]=siluf(v[1])+g_seq[ro0+1]+g_t1[ro0+1];
                    v[2]=siluf(v[2])+g_seq[ro1]+g_t1[ro1];     v[3]=siluf(v[3])+g_seq[ro1+1]+g_t1[ro1+1];
                }
            }
            *(float2*)(Cp+ro0)=make_float2(v[0],v[1]);
            *(float2*)(Cp+ro1)=make_float2(v[2],v[3]);
        }
    }
}

__global__ void conv1d_kernel(const float* ck,const float* cb){
    int row=blockIdx.x,i=threadIdx.x,s=row&1023;
    float acc=cb[i];
    const float* base=g_up+(size_t)row*768+i;
#pragma unroll
    for(int t=0;t<4;t++){int sp=s-3+t; if(sp>=0)acc=fmaf(base[(t-3)*768],ck[i*4+t],acc);}
    g_xact[(size_t)row*NI+i]=siluf(acc);
}

// ---- scan: branchless deferred reduction (ladder issued before FMA loop, no hasp branch) ----
#define TT 32
__device__ __forceinline__ void scan_load_tile(int tile,int buf,int lt,int nth,
    size_t r0,int head,float ksc,
    float (*sQ)[TT][DHD],float (*sK)[TT][DHD],float (*sV)[TT][DHD],
    float (*sZ)[TT][DHD],float (*sX)[TT][DHD],float (*sI)[TT],float (*sF)[TT])
{
    size_t base=(r0+(size_t)tile*TT);
    for(int u=lt;u<1280;u+=nth){
        int arr=u>>8,rem=u&255,step=rem>>3,l4=(rem&7)<<2;
        size_t row=base+step;
        float4 v;
        if(arr==0)      v=*(const float4*)(g_qk  +row*768+     head*DHD+l4);
        else if(arr==1){v=*(const float4*)(g_qk  +row*768+384+ head*DHD+l4);
                        v.x*=ksc;v.y*=ksc;v.z*=ksc;v.w*=ksc;}
        else if(arr==2) v=*(const float4*)(g_up  +row*768+     head*DHD+l4);
        else if(arr==3) v=*(const float4*)(g_up  +row*768+384+ head*DHD+l4);
        else            v=*(const float4*)(g_xact+row*384+     head*DHD+l4);
        float* dst=(arr==0)?&sQ[buf][step][l4]:(arr==1)?&sK[buf][step][l4]:
                   (arr==2)?&sV[buf][step][l4]:(arr==3)?&sZ[buf][step][l4]:&sX[buf][step][l4];
        *(float4*)dst=v;
    }
    for(int u=lt;u<2*TT;u+=nth){
        int step=u>>1;
        size_t row=base+step;
        if(u&1) sF[buf][step]=g_gates[row*64+12+head];
        else    sI[buf][step]=g_gates[row*64+head];
    }
}

__global__ void __launch_bounds__(128) scan_kernel(const float* skip,const float* mhw,const float* mhb){
    const int tid=threadIdx.x,lane=tid&31,wid=tid>>5;
    const int bh=blockIdx.x,b=bh/NHD,head=bh-b*NHD,idx=head*DHD+lane;
    __shared__ float sQ[2][TT][DHD],sK[2][TT][DHD],sV[2][TT][DHD],sZ[2][TT][DHD],sX[2][TT][DHD];
    __shared__ float sI[2][TT],sF[2][TT];
    const float ksc=0.17677669529663687f;
    const size_t r0=(size_t)b*SS;

    scan_load_tile(0,0,tid,128,r0,head,ksc,sQ,sK,sV,sZ,sX,sI,sF);
    __syncthreads();

    float C[DHD];
#pragma unroll
    for(int e=0;e<DHD;e++)C[e]=0.f;
    float nl=0.f,m=0.f;
    const float wg=mhw[idx],bg=mhb[idx],skp=skip[idx];

    // step -1 dummy state: store goes to scratch, values finite
    float pNQ=0.f,pH=0.f,pZ=0.f,pX=0.f;
    float* pDst=&g_scr[idx];

    const int NTILE=SS/TT;
    for(int tile=0;tile<NTILE;tile++){
        int buf=tile&1;
        if(wid>0){
            if(tile+1<NTILE) scan_load_tile(tile+1,buf^1,tid-32,96,r0,head,ksc,sQ,sK,sV,sZ,sX,sI,sF);
        } else {
            for(int t=0;t<TT;t++){
                float cq=sQ[buf][t][lane],ckk=sK[buf][t][lane],cv=sV[buf][t][lane];
                float cz=sZ[buf][t][lane],cx=sX[buf][t][lane];
                float ci=sI[buf][t],cf=sF[buf][t];
                float mnew=fmaxf(cf+m,ci);
                float fs=__expf(cf+m-mnew),is=__expf(ci-mnew);
                m=mnew;
                nl=fs*nl+is*ckk;
                float isv=is*cv;
                // unconditional deferred ladder for previous step (interleaves with FMAs below)
                float rq=pNQ,rs=pH,rr=pH*pH;
#pragma unroll
                for(int o=16;o>0;o>>=1){
                    rq+=__shfl_xor_sync(~0u,rq,o);
                    rs+=__shfl_xor_sync(~0u,rs,o);
                    rr+=__shfl_xor_sync(~0u,rr,o);
                }
                float h0=0.f,h1=0.f,h2=0.f,h3=0.f;
#pragma unroll
                for(int j=0;j<8;j++){
                    float4 k4=*(const float4*)(&sK[buf][t][4*j]),q4=*(const float4*)(&sQ[buf][t][4*j]);
                    C[4*j]  =fmaf(isv,k4.x,fs*C[4*j]);   h0=fmaf(C[4*j],  q4.x,h0);
                    C[4*j+1]=fmaf(isv,k4.y,fs*C[4*j+1]); h1=fmaf(C[4*j+1],q4.y,h1);
                    C[4*j+2]=fmaf(isv,k4.z,fs*C[4*j+2]); h2=fmaf(C[4*j+2],q4.z,h2);
                    C[4*j+3]=fmaf(isv,k4.w,fs*C[4*j+3]); h3=fmaf(C[4*j+3],q4.w,h3);
                }
                float h=(h0+h1)+(h2+h3);
                float nqcur=nl*cq;
                // finalize previous step
                float d=fmaxf(fabsf(rq),1.f);
                float mu=rs*(1.f/32.f),var=rr*(1.f/32.f)-mu*mu;
                float rstd=rsqrtf(var+1e-5f*d*d);
                float hn=(pH-mu)*rstd*wg+bg;
                *pDst=(hn+skp*pX)*siluf(pZ);
                pNQ=nqcur; pH=h; pZ=cz; pX=cx;
                pDst=&g_hout[(r0+(size_t)tile*TT+t)*NI+idx];
            }
        }
        __syncthreads();
    }
    if(wid==0){
        float rq=pNQ,rs=pH,rr=pH*pH;
#pragma unroll
        for(int o=16;o>0;o>>=1){
            rq+=__shfl_xor_sync(~0u,rq,o);
            rs+=__shfl_xor_sync(~0u,rs,o);
            rr+=__shfl_xor_sync(~0u,rr,o);
        }
        float d=fmaxf(fabsf(rq),1.f);
        float mu=rs*(1.f/32.f),var=rr*(1.f/32.f)-mu*mu;
        float rstd=rsqrtf(var+1e-5f*d*d);
        float hn=(pH-mu)*rstd*wg+bg;
        *pDst=(hn+skp*pX)*siluf(pZ);
    }
}

__global__ void bn_stats_kernel(){
    int c=threadIdx.x,blk=blockIdx.x;
    float s=0.f,q=0.f;
    for(int r=0;r<64;r++){float v=g_conv[((size_t)(blk*64+r))*192+c]; s+=v; q+=v*v;}
    g_bnpart[blk*384+c]=s; g_bnpart[blk*384+192+c]=q;
}
__global__ void bn_reduce_kernel(const float* bng,const float* bnb){
    int c=threadIdx.x;
    float s=0.f,q=0.f;
    for(int b=0;b<256;b++){s+=g_bnpart[b*384+c];q+=g_bnpart[b*384+192+c];}
    float mu=s*(1.f/16384.f),var=q*(1.f/16384.f)-mu*mu;
    float a=bng[c]*rsqrtf(var+1e-5f);
    g_bna[c]=a; g_bnb[c]=bnb[c]-mu*a;
}

__global__ void out_bn_kernel(float* out){
    __shared__ float tile[32][193];
    int b=blockIdx.x>>5,p0=(blockIdx.x&31)*32,tid=threadIdx.x;
    for(int i=tid;i<32*192;i+=256){int pi=i/192,c=i-pi*192; tile[pi][c]=g_conv[((size_t)(b*1024+p0+pi))*192+c];}
    __syncthreads();
    for(int i=tid;i<192*32;i+=256){
        int c=i>>5,pi=i&31;
        float v=tile[pi][c]*g_bna[c]+g_bnb[c];
        out[((size_t)b*192+c)*1024+p0+pi]=(v>=0.f)?v:0.01f*v;
    }
}

extern "C" void kernel_launch(void* const* d_in,const int* in_sizes,int n_in,void* d_out,int out_size){
    const float* x=(const float*)d_in[0];
    const float* ln_w=(const float*)d_in[1];
    const float* ln_b=(const float*)d_in[2];
    const float* w_up=(const float*)d_in[3];
    const float* b_up=(const float*)d_in[4];
    const float* conv_k=(const float*)d_in[5];
    const float* conv_b=(const float*)d_in[6];
    const float* w_q=(const float*)d_in[7];
    const float* w_k=(const float*)d_in[8];
    const float* w_i=(const float*)d_in[9];
    const float* b_i=(const float*)d_in[10];
    const float* w_f=(const float*)d_in[11];
    const float* b_f=(const float*)d_in[12];
    const float* skip=(const float*)d_in[13];
    const float* mh_w=(const float*)d_in[14];
    const float* mh_b=(const float*)d_in[15];
    const float* w_down=(const float*)d_in[16];
    const float* b_down=(const float*)d_in[17];
    const float* w_lin=(const float*)d_in[18];
    const float* b_lin=(const float*)d_in[19];
    const float* conv2w=(const float*)d_in[20];
    const float* bn_g=(const float*)d_in[22];
    const float* bn_b=(const float*)d_in[23];
    float* out=(float*)d_out;

    float *p_hln,*p_up,*p_xact,*p_qk,*p_hout,*p_seq,*p_t1,*p_y,*p_wqk,*p_wcomb,*p_gates,*p_wconv,*p_conv;
    cudaGetSymbolAddress((void**)&p_hln,g_hln);
    cudaGetSymbolAddress((void**)&p_up,g_up);
    cudaGetSymbolAddress((void**)&p_xact,g_xact);
    cudaGetSymbolAddress((void**)&p_qk,g_qk);
    cudaGetSymbolAddress((void**)&p_hout,g_hout);
    cudaGetSymbolAddress((void**)&p_seq,g_seq);
    cudaGetSymbolAddress((void**)&p_t1,g_t1);
    cudaGetSymbolAddress((void**)&p_y,g_y);
    cudaGetSymbolAddress((void**)&p_wqk,g_wqk);
    cudaGetSymbolAddress((void**)&p_wcomb,g_wcomb);
    cudaGetSymbolAddress((void**)&p_gates,g_gates);
    cudaGetSymbolAddress((void**)&p_wconv,g_wconv);
    cudaGetSymbolAddress((void**)&p_conv,g_conv);

    prep_gates_kernel<<<1152,256>>>(w_q,w_k,w_i,w_f);
    prep_gates2_kernel<<<192,256>>>(w_i,w_f,b_i,b_f);
    prep_wqk_kernel<<<1152,256>>>(w_q,w_k);
    prep_wconv_kernel<<<1296,256>>>(conv2w);
    transpose_ln_kernel<<<512,256>>>(x,ln_w,ln_b);
    tgemm<0,0><<<dim3(12,128),256>>>(p_hln,w_up,p_up,192,192,768,768,b_up);
    conv1d_kernel<<<NROWS,384>>>(conv_k,conv_b);
    tgemm<0,0><<<dim3(12,128),256>>>(p_xact,p_wqk,p_qk,384,384,768,768,nullptr);
    tgemm<1,2><<<dim3(1,128),256>>>(nullptr,p_wcomb,p_gates,768,0,64,64,nullptr);
    scan_kernel<<<BB*NHD,128>>>(skip,mh_w,mh_b);
    tgemm<0,0><<<dim3(3,128),256>>>(p_hout,w_down,p_t1,384,384,192,192,b_down);
    tgemm<0,3><<<dim3(3,128),256>>>(p_seq,w_lin,p_y,192,192,192,192,b_lin);
    tgemm<2,0><<<dim3(3,128),256>>>(nullptr,p_wconv,p_conv,1728,0,192,192,nullptr);
    bn_stats_kernel<<<256,192>>>();
    bn_reduce_kernel<<<1,192>>>(bn_g,bn_b);
    out_bn_kernel<<<512,256>>>(out);
}